// round 12
// baseline (speedup 1.0000x reference)
#include <cuda_runtime.h>
#include <cuda_bf16.h>
#include <math.h>
#include <stdint.h>

#define NHALF 8192
#define NTOT  16384
#define DDIM  256
#define NTILE_LIN 8256       // 129*128/2 upper-triangle tiles
#define SIM_GRID 296         // persistent: 2 CTAs/SM
#define PSTR  68             // proj: tf32 smem row stride in 4B words (64 + 4)
#define PROJ_SMEM (2 * 128 * PSTR * 4)

// sim: chunked double-buffered smem. Chunk = 128 rows x 128 fp8 cols (128B).
#define CSTR   144                       // chunk row stride bytes (128 + 16)
#define CHUNK_BYTES (128 * CSTR)         // 18432
#define STAGE_BYTES (2 * CHUNK_BYTES)    // A + B = 36864
#define RED_OFF (2 * STAGE_BYTES)        // 73728: epilogue reduce scratch
#define SIM_SMEM (RED_OFF + 8 * 72 * 4)  // + 2304 = 76032

// ---- scratch ----
__device__ float g_a[(size_t)NTOT * DDIM];
__device__ float g_n[(size_t)NTOT * DDIM];
__device__ uint8_t g_n8[(size_t)NTOT * DDIM];   // e4m3 of n * 16
__device__ float g_rs_same[NTOT];
__device__ float g_rs_cross[NTOT];
__device__ float g_s12[NHALF];

static __device__ __forceinline__ uint32_t smem_u32(const void* p) {
    uint32_t a;
    asm("{ .reg .u64 t; cvta.to.shared.u64 t, %1; cvt.u32.u64 %0, t; }"
        : "=r"(a) : "l"(p));
    return a;
}

static __device__ __forceinline__ void ldsm4(uint32_t& r0, uint32_t& r1,
                                             uint32_t& r2, uint32_t& r3,
                                             uint32_t addr) {
    asm volatile("ldmatrix.sync.aligned.m8n8.x4.shared.b16 {%0,%1,%2,%3}, [%4];"
                 : "=r"(r0), "=r"(r1), "=r"(r2), "=r"(r3) : "r"(addr));
}

static __device__ __forceinline__ void mma_fp8(float* d, const uint32_t* a,
                                               uint32_t b0, uint32_t b1) {
    asm volatile(
        "mma.sync.aligned.m16n8k32.row.col.f32.e4m3.e4m3.f32 "
        "{%0,%1,%2,%3}, {%4,%5,%6,%7}, {%8,%9}, {%0,%1,%2,%3};"
        : "+f"(d[0]), "+f"(d[1]), "+f"(d[2]), "+f"(d[3])
        : "r"(a[0]), "r"(a[1]), "r"(a[2]), "r"(a[3]), "r"(b0), "r"(b1));
}

static __device__ __forceinline__ void mma_tf32(float* d, const uint32_t* a,
                                                uint32_t b0, uint32_t b1) {
    asm volatile(
        "mma.sync.aligned.m16n8k8.row.col.f32.tf32.tf32.f32 "
        "{%0,%1,%2,%3}, {%4,%5,%6,%7}, {%8,%9}, {%0,%1,%2,%3};"
        : "+f"(d[0]), "+f"(d[1]), "+f"(d[2]), "+f"(d[3])
        : "r"(a[0]), "r"(a[1]), "r"(a[2]), "r"(a[3]), "r"(b0), "r"(b1));
}

static __device__ __forceinline__ uint32_t f2tf32(float x) {
    uint32_t u;
    asm("cvt.rna.tf32.f32 %0, %1;" : "=r"(u) : "f"(x));
    return u;
}

static __device__ __forceinline__ uint16_t f2e4m3x2(float lo, float hi) {
    uint16_t u;
    asm("cvt.rn.satfinite.e4m3x2.f32 %0, %1, %2;" : "=h"(u) : "f"(hi), "f"(lo));
    return u;
}

#define CP_ASYNC16(dst, src) \
    asm volatile("cp.async.cg.shared.global [%0], [%1], 16;" \
                 :: "r"(dst), "l"(src) : "memory")
#define CP_COMMIT() asm volatile("cp.async.commit_group;" ::: "memory")
#define CP_WAIT(n)  asm volatile("cp.async.wait_group %0;" :: "n"(n) : "memory")

// triangular decode: tile index -> (bi, bj), bj >= bi
static __device__ __forceinline__ void decode_tile(int t, int& bi, int& bj) {
    int b = (int)((257.0 - sqrt(66049.0 - 8.0 * (double)t)) * 0.5);
    if (b < 0) b = 0;
    if (b > 127) b = 127;
    while (b > 0 && b * (257 - b) / 2 > t) b--;
    while (b < 127 && (b + 1) * (257 - (b + 1)) / 2 <= t) b++;
    bi = b;
    bj = b + (t - b * (257 - b) / 2);
}

// ---------------------------------------------------------------------------
// Projection GEMM via tf32 mma.sync (unchanged).
// ---------------------------------------------------------------------------
template <int MODE>
__global__ void __launch_bounds__(256, 2)
proj_tc(const float* __restrict__ A0, const float* __restrict__ A1,
        const float* __restrict__ B,  const float* __restrict__ bias)
{
    extern __shared__ uint32_t psm[];
    uint32_t* sA = psm;
    uint32_t* sB = psm + 128 * PSTR;

    const int tid = threadIdx.x;
    const int wid = tid >> 5, lane = tid & 31;
    const int wr = wid & 3, wc = wid >> 2;
    const int g = lane >> 2, tig = lane & 3;
    const int row0 = blockIdx.y * 128;
    const int col0 = blockIdx.x * 128;

    float d[2][8][4];
#pragma unroll
    for (int mi = 0; mi < 2; mi++)
#pragma unroll
        for (int ni = 0; ni < 8; ni++)
#pragma unroll
            for (int q = 0; q < 4; q++) d[mi][ni][q] = 0.f;

    for (int kc = 0; kc < 4; kc++) {
        __syncthreads();
#pragma unroll
        for (int it = 0; it < 8; it++) {
            int u = tid + it * 256;
            int r = u >> 4;
            int c4 = (u & 15) * 4;
            const float* ap;
            if (MODE == 0) {
                int arow = row0 + r;
                ap = (arow < NHALF) ? (A0 + (size_t)arow * DDIM)
                                    : (A1 + (size_t)(arow - NHALF) * DDIM);
            } else {
                ap = g_a + (size_t)(row0 + r) * DDIM;
            }
            float4 va = *(const float4*)(ap + kc * 64 + c4);
            uint32_t* dA = sA + r * PSTR + c4;
            dA[0] = f2tf32(va.x); dA[1] = f2tf32(va.y);
            dA[2] = f2tf32(va.z); dA[3] = f2tf32(va.w);
            float4 vb = *(const float4*)(B + (size_t)(col0 + r) * DDIM + kc * 64 + c4);
            uint32_t* dB = sB + r * PSTR + c4;
            dB[0] = f2tf32(vb.x); dB[1] = f2tf32(vb.y);
            dB[2] = f2tf32(vb.z); dB[3] = f2tf32(vb.w);
        }
        __syncthreads();

#pragma unroll
        for (int q = 0; q < 8; q++) {
            const int k0 = q * 8;
            uint32_t a[2][4];
#pragma unroll
            for (int mi = 0; mi < 2; mi++) {
                const uint32_t* base = sA + (wr * 32 + mi * 16 + g) * PSTR + k0 + tig;
                a[mi][0] = base[0];
                a[mi][1] = base[8 * PSTR];
                a[mi][2] = base[4];
                a[mi][3] = base[8 * PSTR + 4];
            }
#pragma unroll
            for (int ni = 0; ni < 8; ni++) {
                const uint32_t* bb = sB + (wc * 64 + ni * 8 + g) * PSTR + k0 + tig;
                uint32_t b0 = bb[0], b1 = bb[4];
#pragma unroll
                for (int mi = 0; mi < 2; mi++) mma_tf32(d[mi][ni], a[mi], b0, b1);
            }
        }
    }

    float* C = (MODE == 0) ? g_a : g_n;
#pragma unroll
    for (int mi = 0; mi < 2; mi++) {
        int gr = row0 + wr * 32 + mi * 16 + g;
#pragma unroll
        for (int ni = 0; ni < 8; ni++) {
            int gc = col0 + wc * 64 + ni * 8 + tig * 2;
            float bs0 = bias[gc], bs1 = bias[gc + 1];
            float v0 = d[mi][ni][0] + bs0;
            float v1 = d[mi][ni][1] + bs1;
            float v2 = d[mi][ni][2] + bs0;
            float v3 = d[mi][ni][3] + bs1;
            if (MODE == 0) {
                v0 = v0 > 0.f ? v0 : expm1f(v0);
                v1 = v1 > 0.f ? v1 : expm1f(v1);
                v2 = v2 > 0.f ? v2 : expm1f(v2);
                v3 = v3 > 0.f ? v3 : expm1f(v3);
            }
            C[(size_t)gr * DDIM + gc]           = v0;
            C[(size_t)gr * DDIM + gc + 1]       = v1;
            C[(size_t)(gr + 8) * DDIM + gc]     = v2;
            C[(size_t)(gr + 8) * DDIM + gc + 1] = v3;
        }
    }
}

// ---------------------------------------------------------------------------
// Fused: L2-normalize rows i and i+NHALF, exact fp32 s12, emit e4m3(n*16).
// Also zeroes the row-sum accumulators (replaces zero_kernel).
// ---------------------------------------------------------------------------
__global__ void norm2_kernel() {
    int i = blockIdx.x;
    int t = threadIdx.x;
    if (t == 64)  { g_rs_same[i] = 0.f;  g_rs_cross[i] = 0.f; }
    if (t == 128) { g_rs_same[i + NHALF] = 0.f; g_rs_cross[i + NHALF] = 0.f; }
    float x1 = g_n[(size_t)i * DDIM + t];
    float x2 = g_n[(size_t)(i + NHALF) * DDIM + t];
    float s1 = x1 * x1, s2 = x2 * x2, dp = x1 * x2;
#pragma unroll
    for (int o = 16; o; o >>= 1) {
        s1 += __shfl_xor_sync(0xffffffffu, s1, o);
        s2 += __shfl_xor_sync(0xffffffffu, s2, o);
        dp += __shfl_xor_sync(0xffffffffu, dp, o);
    }
    __shared__ float ws[3][8];
    if ((t & 31) == 0) { ws[0][t >> 5] = s1; ws[1][t >> 5] = s2; ws[2][t >> 5] = dp; }
    __syncthreads();
    float t1 = 0.f, t2 = 0.f, td = 0.f;
#pragma unroll
    for (int w = 0; w < 8; w++) { t1 += ws[0][w]; t2 += ws[1][w]; td += ws[2][w]; }
    float inv1 = 16.f / fmaxf(sqrtf(t1), 1e-12f);   // scale by 16 for e4m3
    float inv2 = 16.f / fmaxf(sqrtf(t2), 1e-12f);
    float v1 = x1 * inv1;
    float v2 = x2 * inv2;
    float n1 = __shfl_down_sync(0xffffffffu, v1, 1);
    float n2 = __shfl_down_sync(0xffffffffu, v2, 1);
    if ((t & 1) == 0) {
        *(uint16_t*)(g_n8 + (size_t)i * DDIM + t)           = f2e4m3x2(v1, n1);
        *(uint16_t*)(g_n8 + (size_t)(i + NHALF) * DDIM + t) = f2e4m3x2(v2, n2);
    }
    if (t == 0) g_s12[i] = td * inv1 * inv2 * 0.00390625f;  // /256 undo 16*16
}

// ---------------------------------------------------------------------------
// Persistent Gram + exp + reductions (e4m3 mma.sync). 296 CTAs loop over
// the 8256 tiles; 2-stage ring pipelines chunk loads ACROSS tile boundaries
// so the epilogue overlaps the next tile's cp.async.
// ---------------------------------------------------------------------------
__global__ void __launch_bounds__(256, 2)
sim_mma()
{
    extern __shared__ char smem[];

    const int tid = threadIdx.x;
    const int wid = tid >> 5, lane = tid & 31;
    const int wr = wid & 3, wc = wid >> 2;
    const uint32_t s0 = smem_u32(smem);

    const int lr = tid >> 3;            // 0..31 row base group (x4 iters)
    const int lcb = (tid & 7) * 16;     // byte within 128B chunk row
    const int lrow = lane & 15;
    const int lkof = (lane >> 4) * 16;

    // issue chunk c of tile (bi,bj) into stage s (chunk c -> stage c by convention)
    auto issue_chunk = [&](int bi, int bj, int c) {
        uint32_t dA = s0 + c * STAGE_BYTES;
        uint32_t dB = dA + CHUNK_BYTES;
        const char* sa = (const char*)g_n8 + (size_t)(bi * 128) * DDIM + c * 128 + lcb;
        const char* sb = (const char*)g_n8 + (size_t)(bj * 128) * DDIM + c * 128 + lcb;
#pragma unroll
        for (int it = 0; it < 4; it++) {
            int r = lr + it * 32;
            CP_ASYNC16(dA + r * CSTR + lcb, sa + (size_t)r * DDIM);
            CP_ASYNC16(dB + r * CSTR + lcb, sb + (size_t)r * DDIM);
        }
        CP_COMMIT();
    };

    int t = blockIdx.x;
    if (t < NTILE_LIN) {
        int bi, bj;
        decode_tile(t, bi, bj);
        issue_chunk(bi, bj, 0);
        issue_chunk(bi, bj, 1);
    }

    for (; t < NTILE_LIN; t += SIM_GRID) {
        int bi, bj;
        decode_tile(t, bi, bj);
        const int row0 = bi * 128, col0 = bj * 128;
        const int tn = t + SIM_GRID;
        int bi2 = 0, bj2 = 0;
        const bool has_next = tn < NTILE_LIN;
        if (has_next) decode_tile(tn, bi2, bj2);

        float d[2][8][4];
#pragma unroll
        for (int mi = 0; mi < 2; mi++)
#pragma unroll
            for (int ni = 0; ni < 8; ni++)
#pragma unroll
                for (int q = 0; q < 4; q++) d[mi][ni][q] = 0.f;

#pragma unroll
        for (int c = 0; c < 2; c++) {
            CP_WAIT(1);                 // FIFO: oldest pending group done
            __syncthreads();
            const uint32_t sA = s0 + c * STAGE_BYTES;
            const uint32_t sB = sA + CHUNK_BYTES;
#pragma unroll
            for (int q = 0; q < 4; q++) {
                const int kb = q * 32;
                uint32_t a[2][4];
#pragma unroll
                for (int mi = 0; mi < 2; mi++) {
                    uint32_t addr = sA + (wr * 32 + mi * 16 + lrow) * CSTR + kb + lkof;
                    ldsm4(a[mi][0], a[mi][1], a[mi][2], a[mi][3], addr);
                }
                uint32_t b0[8], b1[8];
#pragma unroll
                for (int nq = 0; nq < 4; nq++) {
                    uint32_t addr = sB + (wc * 64 + nq * 16 + lrow) * CSTR + kb + lkof;
                    uint32_t q0, q1, q2, q3;
                    ldsm4(q0, q1, q2, q3, addr);
                    b0[nq * 2] = q0;     b1[nq * 2] = q2;
                    b0[nq * 2 + 1] = q1; b1[nq * 2 + 1] = q3;
                }
#pragma unroll
                for (int mi = 0; mi < 2; mi++)
#pragma unroll
                    for (int ni = 0; ni < 8; ni++)
                        mma_fp8(d[mi][ni], a[mi], b0[ni], b1[ni]);
            }
            __syncthreads();            // stage c fully consumed
            if (has_next) issue_chunk(bi2, bj2, c);   // refill behind us
        }

        // ---- epilogue (overlaps next tile's cp.async) ----
        const bool same = ((bi < 64) == (bj < 64));
        float* rs = same ? g_rs_same : g_rs_cross;
        const float ESC = 0.0078125f;   // 2/256

        float cp0[8], cp1[8];
#pragma unroll
        for (int ni = 0; ni < 8; ni++) { cp0[ni] = 0.f; cp1[ni] = 0.f; }

#pragma unroll
        for (int mi = 0; mi < 2; mi++) {
            float rp0 = 0.f, rp1 = 0.f;
#pragma unroll
            for (int ni = 0; ni < 8; ni++) {
                float e0 = __expf(ESC * d[mi][ni][0]);
                float e1 = __expf(ESC * d[mi][ni][1]);
                float e2 = __expf(ESC * d[mi][ni][2]);
                float e3 = __expf(ESC * d[mi][ni][3]);
                rp0 += e0 + e1;  rp1 += e2 + e3;
                cp0[ni] += e0 + e2;  cp1[ni] += e1 + e3;
            }
            rp0 += __shfl_xor_sync(0xffffffffu, rp0, 1);
            rp0 += __shfl_xor_sync(0xffffffffu, rp0, 2);
            rp1 += __shfl_xor_sync(0xffffffffu, rp1, 1);
            rp1 += __shfl_xor_sync(0xffffffffu, rp1, 2);
            if ((lane & 3) == 0) {
                int br = row0 + wr * 32 + mi * 16 + (lane >> 2);
                atomicAdd(&rs[br], rp0);
                atomicAdd(&rs[br + 8], rp1);
            }
        }

        if (bi != bj) {
#pragma unroll
            for (int ni = 0; ni < 8; ni++) {
                cp0[ni] += __shfl_xor_sync(0xffffffffu, cp0[ni], 4);
                cp0[ni] += __shfl_xor_sync(0xffffffffu, cp0[ni], 8);
                cp0[ni] += __shfl_xor_sync(0xffffffffu, cp0[ni], 16);
                cp1[ni] += __shfl_xor_sync(0xffffffffu, cp1[ni], 4);
                cp1[ni] += __shfl_xor_sync(0xffffffffu, cp1[ni], 8);
                cp1[ni] += __shfl_xor_sync(0xffffffffu, cp1[ni], 16);
            }
            float* red = (float*)(smem + RED_OFF);   // separate from stages
            if (lane < 4) {
#pragma unroll
                for (int ni = 0; ni < 8; ni++) {
                    red[wid * 72 + ni * 8 + lane * 2]     = cp0[ni];
                    red[wid * 72 + ni * 8 + lane * 2 + 1] = cp1[ni];
                }
            }
            __syncthreads();
            if (tid < 128) {
                int cwc = tid >> 6;
                int idx = tid & 63;
                float s = red[(cwc * 4 + 0) * 72 + idx]
                        + red[(cwc * 4 + 1) * 72 + idx]
                        + red[(cwc * 4 + 2) * 72 + idx]
                        + red[(cwc * 4 + 3) * 72 + idx];
                atomicAdd(&rs[col0 + tid], s);
            }
            __syncthreads();            // red safe for next tile
        }
    }
}

__global__ void finalize_kernel(float* __restrict__ out) {
    int i = blockIdx.x * blockDim.x + threadIdx.x;
    if (i >= NHALF) return;
    const float E2 = 7.389056098930650f;   // exp(2) diagonal term (||n||=1)
    float den1 = g_rs_same[i] + g_rs_cross[i] - E2;
    float den2 = g_rs_same[i + NHALF] + g_rs_cross[i + NHALF] - E2;
    float twos = 2.0f * g_s12[i];
    out[i] = 0.5f * ((logf(den1) - twos) + (logf(den2) - twos));
}

extern "C" void kernel_launch(void* const* d_in, const int* in_sizes, int n_in,
                              void* d_out, int out_size) {
    const float* z1 = (const float*)d_in[0];
    const float* z2 = (const float*)d_in[1];
    const float* W1 = (const float*)d_in[2];
    const float* b1 = (const float*)d_in[3];
    const float* W2 = (const float*)d_in[4];
    const float* b2 = (const float*)d_in[5];
    float* out = (float*)d_out;

    cudaFuncSetAttribute(sim_mma, cudaFuncAttributeMaxDynamicSharedMemorySize,
                         SIM_SMEM);
    cudaFuncSetAttribute(proj_tc<0>, cudaFuncAttributeMaxDynamicSharedMemorySize,
                         PROJ_SMEM);
    cudaFuncSetAttribute(proj_tc<1>, cudaFuncAttributeMaxDynamicSharedMemorySize,
                         PROJ_SMEM);

    proj_tc<0><<<dim3(2, 128), 256, PROJ_SMEM>>>(z1, z2, W1, b1);
    proj_tc<1><<<dim3(2, 128), 256, PROJ_SMEM>>>(nullptr, nullptr, W2, b2);
    norm2_kernel<<<NHALF, 256>>>();
    sim_mma<<<SIM_GRID, 256, SIM_SMEM>>>();
    finalize_kernel<<<NHALF / 256, 256>>>(out);
}

// round 13
// speedup vs baseline: 1.2946x; 1.2946x over previous
#include <cuda_runtime.h>
#include <cuda_bf16.h>
#include <math.h>
#include <stdint.h>

#define NHALF 8192
#define NTOT  16384
#define DDIM  256
#define NTILE_LIN 8256       // 129*128/2 upper-triangle tiles
#define PSTR  68             // proj: tf32 smem row stride in 4B words (64 + 4)
#define PROJ_SMEM (2 * 128 * PSTR * 4)

// sim: chunked double-buffered smem. Chunk = 128 rows x 128 fp8 cols (128B).
#define CSTR   144                       // chunk row stride bytes (128 + 16)
#define CHUNK_BYTES (128 * CSTR)         // 18432
#define STAGE_BYTES (2 * CHUNK_BYTES)    // A + B = 36864
#define SIM_SMEM (2 * STAGE_BYTES)       // 2 stages = 73728

// ---- scratch ----
__device__ float g_a[(size_t)NTOT * DDIM];
__device__ float g_n[(size_t)NTOT * DDIM];
__device__ uint8_t g_n8[(size_t)NTOT * DDIM];   // e4m3 of n * 16
__device__ float g_rs_same[NTOT];
__device__ float g_rs_cross[NTOT];
__device__ float g_s12[NHALF];

static __device__ __forceinline__ uint32_t smem_u32(const void* p) {
    uint32_t a;
    asm("{ .reg .u64 t; cvta.to.shared.u64 t, %1; cvt.u32.u64 %0, t; }"
        : "=r"(a) : "l"(p));
    return a;
}

static __device__ __forceinline__ void ldsm4(uint32_t& r0, uint32_t& r1,
                                             uint32_t& r2, uint32_t& r3,
                                             uint32_t addr) {
    asm volatile("ldmatrix.sync.aligned.m8n8.x4.shared.b16 {%0,%1,%2,%3}, [%4];"
                 : "=r"(r0), "=r"(r1), "=r"(r2), "=r"(r3) : "r"(addr));
}

static __device__ __forceinline__ void mma_fp8(float* d, const uint32_t* a,
                                               uint32_t b0, uint32_t b1) {
    asm volatile(
        "mma.sync.aligned.m16n8k32.row.col.f32.e4m3.e4m3.f32 "
        "{%0,%1,%2,%3}, {%4,%5,%6,%7}, {%8,%9}, {%0,%1,%2,%3};"
        : "+f"(d[0]), "+f"(d[1]), "+f"(d[2]), "+f"(d[3])
        : "r"(a[0]), "r"(a[1]), "r"(a[2]), "r"(a[3]), "r"(b0), "r"(b1));
}

static __device__ __forceinline__ void mma_tf32(float* d, const uint32_t* a,
                                                uint32_t b0, uint32_t b1) {
    asm volatile(
        "mma.sync.aligned.m16n8k8.row.col.f32.tf32.tf32.f32 "
        "{%0,%1,%2,%3}, {%4,%5,%6,%7}, {%8,%9}, {%0,%1,%2,%3};"
        : "+f"(d[0]), "+f"(d[1]), "+f"(d[2]), "+f"(d[3])
        : "r"(a[0]), "r"(a[1]), "r"(a[2]), "r"(a[3]), "r"(b0), "r"(b1));
}

static __device__ __forceinline__ uint32_t f2tf32(float x) {
    uint32_t u;
    asm("cvt.rna.tf32.f32 %0, %1;" : "=r"(u) : "f"(x));
    return u;
}

static __device__ __forceinline__ uint16_t f2e4m3x2(float lo, float hi) {
    uint16_t u;
    asm("cvt.rn.satfinite.e4m3x2.f32 %0, %1, %2;" : "=h"(u) : "f"(hi), "f"(lo));
    return u;
}

// raw ex2.approx: e = 2^x  (one MUFU; caller folds all scale constants)
static __device__ __forceinline__ float ex2(float x) {
    float r;
    asm("ex2.approx.ftz.f32 %0, %1;" : "=f"(r) : "f"(x));
    return r;
}

#define CP_ASYNC16(dst, src) \
    asm volatile("cp.async.cg.shared.global [%0], [%1], 16;" \
                 :: "r"(dst), "l"(src) : "memory")
#define CP_COMMIT() asm volatile("cp.async.commit_group;" ::: "memory")
#define CP_WAIT(n)  asm volatile("cp.async.wait_group %0;" :: "n"(n) : "memory")

// ---------------------------------------------------------------------------
// Projection GEMM via tf32 mma.sync (unchanged).
// ---------------------------------------------------------------------------
template <int MODE>
__global__ void __launch_bounds__(256, 2)
proj_tc(const float* __restrict__ A0, const float* __restrict__ A1,
        const float* __restrict__ B,  const float* __restrict__ bias)
{
    extern __shared__ uint32_t psm[];
    uint32_t* sA = psm;
    uint32_t* sB = psm + 128 * PSTR;

    const int tid = threadIdx.x;
    const int wid = tid >> 5, lane = tid & 31;
    const int wr = wid & 3, wc = wid >> 2;
    const int g = lane >> 2, tig = lane & 3;
    const int row0 = blockIdx.y * 128;
    const int col0 = blockIdx.x * 128;

    float d[2][8][4];
#pragma unroll
    for (int mi = 0; mi < 2; mi++)
#pragma unroll
        for (int ni = 0; ni < 8; ni++)
#pragma unroll
            for (int q = 0; q < 4; q++) d[mi][ni][q] = 0.f;

    for (int kc = 0; kc < 4; kc++) {
        __syncthreads();
#pragma unroll
        for (int it = 0; it < 8; it++) {
            int u = tid + it * 256;
            int r = u >> 4;
            int c4 = (u & 15) * 4;
            const float* ap;
            if (MODE == 0) {
                int arow = row0 + r;
                ap = (arow < NHALF) ? (A0 + (size_t)arow * DDIM)
                                    : (A1 + (size_t)(arow - NHALF) * DDIM);
            } else {
                ap = g_a + (size_t)(row0 + r) * DDIM;
            }
            float4 va = *(const float4*)(ap + kc * 64 + c4);
            uint32_t* dA = sA + r * PSTR + c4;
            dA[0] = f2tf32(va.x); dA[1] = f2tf32(va.y);
            dA[2] = f2tf32(va.z); dA[3] = f2tf32(va.w);
            float4 vb = *(const float4*)(B + (size_t)(col0 + r) * DDIM + kc * 64 + c4);
            uint32_t* dB = sB + r * PSTR + c4;
            dB[0] = f2tf32(vb.x); dB[1] = f2tf32(vb.y);
            dB[2] = f2tf32(vb.z); dB[3] = f2tf32(vb.w);
        }
        __syncthreads();

#pragma unroll
        for (int q = 0; q < 8; q++) {
            const int k0 = q * 8;
            uint32_t a[2][4];
#pragma unroll
            for (int mi = 0; mi < 2; mi++) {
                const uint32_t* base = sA + (wr * 32 + mi * 16 + g) * PSTR + k0 + tig;
                a[mi][0] = base[0];
                a[mi][1] = base[8 * PSTR];
                a[mi][2] = base[4];
                a[mi][3] = base[8 * PSTR + 4];
            }
#pragma unroll
            for (int ni = 0; ni < 8; ni++) {
                const uint32_t* bb = sB + (wc * 64 + ni * 8 + g) * PSTR + k0 + tig;
                uint32_t b0 = bb[0], b1 = bb[4];
#pragma unroll
                for (int mi = 0; mi < 2; mi++) mma_tf32(d[mi][ni], a[mi], b0, b1);
            }
        }
    }

    float* C = (MODE == 0) ? g_a : g_n;
#pragma unroll
    for (int mi = 0; mi < 2; mi++) {
        int gr = row0 + wr * 32 + mi * 16 + g;
#pragma unroll
        for (int ni = 0; ni < 8; ni++) {
            int gc = col0 + wc * 64 + ni * 8 + tig * 2;
            float bs0 = bias[gc], bs1 = bias[gc + 1];
            float v0 = d[mi][ni][0] + bs0;
            float v1 = d[mi][ni][1] + bs1;
            float v2 = d[mi][ni][2] + bs0;
            float v3 = d[mi][ni][3] + bs1;
            if (MODE == 0) {
                v0 = v0 > 0.f ? v0 : expm1f(v0);
                v1 = v1 > 0.f ? v1 : expm1f(v1);
                v2 = v2 > 0.f ? v2 : expm1f(v2);
                v3 = v3 > 0.f ? v3 : expm1f(v3);
            }
            C[(size_t)gr * DDIM + gc]           = v0;
            C[(size_t)gr * DDIM + gc + 1]       = v1;
            C[(size_t)(gr + 8) * DDIM + gc]     = v2;
            C[(size_t)(gr + 8) * DDIM + gc + 1] = v3;
        }
    }
}

// ---------------------------------------------------------------------------
// Fused: L2-normalize rows i and i+NHALF, exact fp32 s12, emit e4m3(n*16).
// Also zeroes the row-sum accumulators.
// ---------------------------------------------------------------------------
__global__ void norm2_kernel() {
    int i = blockIdx.x;
    int t = threadIdx.x;
    if (t == 64)  { g_rs_same[i] = 0.f;  g_rs_cross[i] = 0.f; }
    if (t == 128) { g_rs_same[i + NHALF] = 0.f; g_rs_cross[i + NHALF] = 0.f; }
    float x1 = g_n[(size_t)i * DDIM + t];
    float x2 = g_n[(size_t)(i + NHALF) * DDIM + t];
    float s1 = x1 * x1, s2 = x2 * x2, dp = x1 * x2;
#pragma unroll
    for (int o = 16; o; o >>= 1) {
        s1 += __shfl_xor_sync(0xffffffffu, s1, o);
        s2 += __shfl_xor_sync(0xffffffffu, s2, o);
        dp += __shfl_xor_sync(0xffffffffu, dp, o);
    }
    __shared__ float ws[3][8];
    if ((t & 31) == 0) { ws[0][t >> 5] = s1; ws[1][t >> 5] = s2; ws[2][t >> 5] = dp; }
    __syncthreads();
    float t1 = 0.f, t2 = 0.f, td = 0.f;
#pragma unroll
    for (int w = 0; w < 8; w++) { t1 += ws[0][w]; t2 += ws[1][w]; td += ws[2][w]; }
    float inv1 = 16.f / fmaxf(sqrtf(t1), 1e-12f);   // scale by 16 for e4m3
    float inv2 = 16.f / fmaxf(sqrtf(t2), 1e-12f);
    float v1 = x1 * inv1;
    float v2 = x2 * inv2;
    float n1 = __shfl_down_sync(0xffffffffu, v1, 1);
    float n2 = __shfl_down_sync(0xffffffffu, v2, 1);
    if ((t & 1) == 0) {
        *(uint16_t*)(g_n8 + (size_t)i * DDIM + t)           = f2e4m3x2(v1, n1);
        *(uint16_t*)(g_n8 + (size_t)(i + NHALF) * DDIM + t) = f2e4m3x2(v2, n2);
    }
    if (t == 0) g_s12[i] = td * inv1 * inv2 * 0.00390625f;  // /256 undo 16*16
}

// ---------------------------------------------------------------------------
// Gram + exp + reductions via e4m3 mma.sync m16n8k32. 128x128x256 per CTA.
// 2 chunks of 128B, double-buffered cp.async, 2 CTAs/SM (R11 structure).
// Epilogue: single-FMUL + MUFU exp; mainloop: hoisted ldsm bases.
// ---------------------------------------------------------------------------
__global__ void __launch_bounds__(256, 2)
sim_mma()
{
    extern __shared__ char smem[];

    const int t = blockIdx.x;
    int bi = (int)((257.0 - sqrt(66049.0 - 8.0 * (double)t)) * 0.5);
    if (bi < 0) bi = 0;
    if (bi > 127) bi = 127;
    while (bi > 0 && bi * (257 - bi) / 2 > t) bi--;
    while (bi < 127 && (bi + 1) * (257 - (bi + 1)) / 2 <= t) bi++;
    const int bj = bi + (t - bi * (257 - bi) / 2);

    const int tid = threadIdx.x;
    const int wid = tid >> 5, lane = tid & 31;
    const int wr = wid & 3, wc = wid >> 2;
    const int row0 = bi * 128, col0 = bj * 128;

    const uint32_t s0 = smem_u32(smem);
    const char* srcA = (const char*)g_n8 + (size_t)row0 * DDIM;
    const char* srcB = (const char*)g_n8 + (size_t)col0 * DDIM;

    const int lr = tid >> 3;            // 0..31 row base group (x4 iters)
    const int lcb = (tid & 7) * 16;     // byte within 128B chunk row

    auto issue_chunk = [&](int c, int s) {
        uint32_t dA = s0 + s * STAGE_BYTES;
        uint32_t dB = dA + CHUNK_BYTES;
        const char* sa = srcA + c * 128 + lcb;
        const char* sb = srcB + c * 128 + lcb;
#pragma unroll
        for (int it = 0; it < 4; it++) {
            int r = lr + it * 32;
            CP_ASYNC16(dA + r * CSTR + lcb, sa + (size_t)r * DDIM);
            CP_ASYNC16(dB + r * CSTR + lcb, sb + (size_t)r * DDIM);
        }
        CP_COMMIT();
    };

    issue_chunk(0, 0);
    issue_chunk(1, 1);

    float d[2][8][4];
#pragma unroll
    for (int mi = 0; mi < 2; mi++)
#pragma unroll
        for (int ni = 0; ni < 8; ni++)
#pragma unroll
            for (int q = 0; q < 4; q++) d[mi][ni][q] = 0.f;

    const int lrow = lane & 15;
    const int lkof = (lane >> 4) * 16;

    // hoisted ldsm offsets (relative to stage base)
    const uint32_t offA0 = (uint32_t)((wr * 32 + lrow) * CSTR + lkof);
    const uint32_t offA1 = offA0 + 16 * CSTR;
    const uint32_t offB0 = (uint32_t)(CHUNK_BYTES + (wc * 64 + lrow) * CSTR + lkof);
    const uint32_t offB1 = offB0 + 16 * CSTR;
    const uint32_t offB2 = offB0 + 32 * CSTR;
    const uint32_t offB3 = offB0 + 48 * CSTR;

#pragma unroll
    for (int c = 0; c < 2; c++) {
        if (c == 0) CP_WAIT(1); else CP_WAIT(0);
        __syncthreads();
        const uint32_t sbase = s0 + c * STAGE_BYTES;
#pragma unroll
        for (int q = 0; q < 4; q++) {
            const uint32_t kb = sbase + q * 32;
            uint32_t a[2][4];
            ldsm4(a[0][0], a[0][1], a[0][2], a[0][3], kb + offA0);
            ldsm4(a[1][0], a[1][1], a[1][2], a[1][3], kb + offA1);
            uint32_t b0[8], b1[8];
            {
                uint32_t q0, q1, q2, q3;
                ldsm4(q0, q1, q2, q3, kb + offB0);
                b0[0] = q0; b1[0] = q2; b0[1] = q1; b1[1] = q3;
                ldsm4(q0, q1, q2, q3, kb + offB1);
                b0[2] = q0; b1[2] = q2; b0[3] = q1; b1[3] = q3;
                ldsm4(q0, q1, q2, q3, kb + offB2);
                b0[4] = q0; b1[4] = q2; b0[5] = q1; b1[5] = q3;
                ldsm4(q0, q1, q2, q3, kb + offB3);
                b0[6] = q0; b1[6] = q2; b0[7] = q1; b1[7] = q3;
            }
#pragma unroll
            for (int mi = 0; mi < 2; mi++)
#pragma unroll
                for (int ni = 0; ni < 8; ni++)
                    mma_fp8(d[mi][ni], a[mi], b0[ni], b1[ni]);
        }
        __syncthreads();
    }

    // ---- epilogue: exp2(acc * ESC2), row sums, col sums ----
    const bool same = ((bi < 64) == (bj < 64));
    float* rs = same ? g_rs_same : g_rs_cross;
    // (2/256) * log2(e): fold operand descale, 1/tau, and ex2 base change
    const float ESC2 = 0.011271059930f;

    float cp0[8], cp1[8];
#pragma unroll
    for (int ni = 0; ni < 8; ni++) { cp0[ni] = 0.f; cp1[ni] = 0.f; }

#pragma unroll
    for (int mi = 0; mi < 2; mi++) {
        float rp0 = 0.f, rp1 = 0.f;
#pragma unroll
        for (int ni = 0; ni < 8; ni++) {
            float e0 = ex2(ESC2 * d[mi][ni][0]);
            float e1 = ex2(ESC2 * d[mi][ni][1]);
            float e2 = ex2(ESC2 * d[mi][ni][2]);
            float e3 = ex2(ESC2 * d[mi][ni][3]);
            rp0 += e0 + e1;  rp1 += e2 + e3;
            cp0[ni] += e0 + e2;  cp1[ni] += e1 + e3;
        }
        rp0 += __shfl_xor_sync(0xffffffffu, rp0, 1);
        rp0 += __shfl_xor_sync(0xffffffffu, rp0, 2);
        rp1 += __shfl_xor_sync(0xffffffffu, rp1, 1);
        rp1 += __shfl_xor_sync(0xffffffffu, rp1, 2);
        if ((lane & 3) == 0) {
            int br = row0 + wr * 32 + mi * 16 + (lane >> 2);
            atomicAdd(&rs[br], rp0);
            atomicAdd(&rs[br + 8], rp1);
        }
    }

    if (bi != bj) {
#pragma unroll
        for (int ni = 0; ni < 8; ni++) {
            cp0[ni] += __shfl_xor_sync(0xffffffffu, cp0[ni], 4);
            cp0[ni] += __shfl_xor_sync(0xffffffffu, cp0[ni], 8);
            cp0[ni] += __shfl_xor_sync(0xffffffffu, cp0[ni], 16);
            cp1[ni] += __shfl_xor_sync(0xffffffffu, cp1[ni], 4);
            cp1[ni] += __shfl_xor_sync(0xffffffffu, cp1[ni], 8);
            cp1[ni] += __shfl_xor_sync(0xffffffffu, cp1[ni], 16);
        }
        float* red = (float*)smem;   // stages dead; CTA exits after this
        if (lane < 4) {
#pragma unroll
            for (int ni = 0; ni < 8; ni++) {
                red[wid * 72 + ni * 8 + lane * 2]     = cp0[ni];
                red[wid * 72 + ni * 8 + lane * 2 + 1] = cp1[ni];
            }
        }
        __syncthreads();
        if (tid < 128) {
            int cwc = tid >> 6;
            int idx = tid & 63;
            float s = red[(cwc * 4 + 0) * 72 + idx]
                    + red[(cwc * 4 + 1) * 72 + idx]
                    + red[(cwc * 4 + 2) * 72 + idx]
                    + red[(cwc * 4 + 3) * 72 + idx];
            atomicAdd(&rs[col0 + tid], s);
        }
    }
}

__global__ void finalize_kernel(float* __restrict__ out) {
    int i = blockIdx.x * blockDim.x + threadIdx.x;
    if (i >= NHALF) return;
    const float E2 = 7.389056098930650f;   // exp(2) diagonal term (||n||=1)
    float den1 = g_rs_same[i] + g_rs_cross[i] - E2;
    float den2 = g_rs_same[i + NHALF] + g_rs_cross[i + NHALF] - E2;
    float twos = 2.0f * g_s12[i];
    out[i] = 0.5f * ((logf(den1) - twos) + (logf(den2) - twos));
}

extern "C" void kernel_launch(void* const* d_in, const int* in_sizes, int n_in,
                              void* d_out, int out_size) {
    const float* z1 = (const float*)d_in[0];
    const float* z2 = (const float*)d_in[1];
    const float* W1 = (const float*)d_in[2];
    const float* b1 = (const float*)d_in[3];
    const float* W2 = (const float*)d_in[4];
    const float* b2 = (const float*)d_in[5];
    float* out = (float*)d_out;

    cudaFuncSetAttribute(sim_mma, cudaFuncAttributeMaxDynamicSharedMemorySize,
                         SIM_SMEM);
    cudaFuncSetAttribute(proj_tc<0>, cudaFuncAttributeMaxDynamicSharedMemorySize,
                         PROJ_SMEM);
    cudaFuncSetAttribute(proj_tc<1>, cudaFuncAttributeMaxDynamicSharedMemorySize,
                         PROJ_SMEM);

    proj_tc<0><<<dim3(2, 128), 256, PROJ_SMEM>>>(z1, z2, W1, b1);
    proj_tc<1><<<dim3(2, 128), 256, PROJ_SMEM>>>(nullptr, nullptr, W2, b2);
    norm2_kernel<<<NHALF, 256>>>();
    sim_mma<<<NTILE_LIN, 256, SIM_SMEM>>>();
    finalize_kernel<<<NHALF / 256, 256>>>(out);
}

// round 14
// speedup vs baseline: 1.3059x; 1.0087x over previous
#include <cuda_runtime.h>
#include <cuda_bf16.h>
#include <math.h>
#include <stdint.h>

#define NHALF 8192
#define NTOT  16384
#define DDIM  256
#define NTILE_LIN 8256       // 129*128/2 upper-triangle tiles
#define PSTR  68             // proj: tf32 smem row stride in 4B words (64 + 4)
#define PROJ_SMEM (2 * 128 * PSTR * 4)

// sim: chunked smem. Chunk = 128 rows x 128 fp8 cols (128B).
#define CSTR   144                       // chunk row stride bytes (128 + 16)
#define CHUNK_BYTES (128 * CSTR)         // 18432
#define STAGE_BYTES (2 * CHUNK_BYTES)    // A + B = 36864
#define SIM_SMEM (2 * STAGE_BYTES)       // 2 stages = 73728

// ---- scratch ----
__device__ float g_a[(size_t)NTOT * DDIM];
__device__ float g_n[(size_t)NTOT * DDIM];
__device__ uint8_t g_n8[(size_t)NTOT * DDIM];   // e4m3 of n * 16
__device__ float g_rs_same[NTOT];
__device__ float g_rs_cross[NTOT];
__device__ float g_s12[NHALF];

static __device__ __forceinline__ uint32_t smem_u32(const void* p) {
    uint32_t a;
    asm("{ .reg .u64 t; cvta.to.shared.u64 t, %1; cvt.u32.u64 %0, t; }"
        : "=r"(a) : "l"(p));
    return a;
}

static __device__ __forceinline__ void ldsm4(uint32_t& r0, uint32_t& r1,
                                             uint32_t& r2, uint32_t& r3,
                                             uint32_t addr) {
    asm volatile("ldmatrix.sync.aligned.m8n8.x4.shared.b16 {%0,%1,%2,%3}, [%4];"
                 : "=r"(r0), "=r"(r1), "=r"(r2), "=r"(r3) : "r"(addr));
}

static __device__ __forceinline__ void mma_fp8(float* d, const uint32_t* a,
                                               uint32_t b0, uint32_t b1) {
    asm volatile(
        "mma.sync.aligned.m16n8k32.row.col.f32.e4m3.e4m3.f32 "
        "{%0,%1,%2,%3}, {%4,%5,%6,%7}, {%8,%9}, {%0,%1,%2,%3};"
        : "+f"(d[0]), "+f"(d[1]), "+f"(d[2]), "+f"(d[3])
        : "r"(a[0]), "r"(a[1]), "r"(a[2]), "r"(a[3]), "r"(b0), "r"(b1));
}

static __device__ __forceinline__ void mma_tf32(float* d, const uint32_t* a,
                                                uint32_t b0, uint32_t b1) {
    asm volatile(
        "mma.sync.aligned.m16n8k8.row.col.f32.tf32.tf32.f32 "
        "{%0,%1,%2,%3}, {%4,%5,%6,%7}, {%8,%9}, {%0,%1,%2,%3};"
        : "+f"(d[0]), "+f"(d[1]), "+f"(d[2]), "+f"(d[3])
        : "r"(a[0]), "r"(a[1]), "r"(a[2]), "r"(a[3]), "r"(b0), "r"(b1));
}

static __device__ __forceinline__ uint32_t f2tf32(float x) {
    uint32_t u;
    asm("cvt.rna.tf32.f32 %0, %1;" : "=r"(u) : "f"(x));
    return u;
}

static __device__ __forceinline__ uint16_t f2e4m3x2(float lo, float hi) {
    uint16_t u;
    asm("cvt.rn.satfinite.e4m3x2.f32 %0, %1, %2;" : "=h"(u) : "f"(hi), "f"(lo));
    return u;
}

// raw ex2.approx: e = 2^x  (one MUFU; caller folds all scale constants)
static __device__ __forceinline__ float ex2(float x) {
    float r;
    asm("ex2.approx.ftz.f32 %0, %1;" : "=f"(r) : "f"(x));
    return r;
}

#define CP_ASYNC16(dst, src) \
    asm volatile("cp.async.cg.shared.global [%0], [%1], 16;" \
                 :: "r"(dst), "l"(src) : "memory")
#define CP_COMMIT() asm volatile("cp.async.commit_group;" ::: "memory")
#define CP_WAIT(n)  asm volatile("cp.async.wait_group %0;" :: "n"(n) : "memory")

// ---------------------------------------------------------------------------
// Projection GEMM via tf32 mma.sync (unchanged).
// ---------------------------------------------------------------------------
template <int MODE>
__global__ void __launch_bounds__(256, 2)
proj_tc(const float* __restrict__ A0, const float* __restrict__ A1,
        const float* __restrict__ B,  const float* __restrict__ bias)
{
    extern __shared__ uint32_t psm[];
    uint32_t* sA = psm;
    uint32_t* sB = psm + 128 * PSTR;

    const int tid = threadIdx.x;
    const int wid = tid >> 5, lane = tid & 31;
    const int wr = wid & 3, wc = wid >> 2;
    const int g = lane >> 2, tig = lane & 3;
    const int row0 = blockIdx.y * 128;
    const int col0 = blockIdx.x * 128;

    float d[2][8][4];
#pragma unroll
    for (int mi = 0; mi < 2; mi++)
#pragma unroll
        for (int ni = 0; ni < 8; ni++)
#pragma unroll
            for (int q = 0; q < 4; q++) d[mi][ni][q] = 0.f;

    for (int kc = 0; kc < 4; kc++) {
        __syncthreads();
#pragma unroll
        for (int it = 0; it < 8; it++) {
            int u = tid + it * 256;
            int r = u >> 4;
            int c4 = (u & 15) * 4;
            const float* ap;
            if (MODE == 0) {
                int arow = row0 + r;
                ap = (arow < NHALF) ? (A0 + (size_t)arow * DDIM)
                                    : (A1 + (size_t)(arow - NHALF) * DDIM);
            } else {
                ap = g_a + (size_t)(row0 + r) * DDIM;
            }
            float4 va = *(const float4*)(ap + kc * 64 + c4);
            uint32_t* dA = sA + r * PSTR + c4;
            dA[0] = f2tf32(va.x); dA[1] = f2tf32(va.y);
            dA[2] = f2tf32(va.z); dA[3] = f2tf32(va.w);
            float4 vb = *(const float4*)(B + (size_t)(col0 + r) * DDIM + kc * 64 + c4);
            uint32_t* dB = sB + r * PSTR + c4;
            dB[0] = f2tf32(vb.x); dB[1] = f2tf32(vb.y);
            dB[2] = f2tf32(vb.z); dB[3] = f2tf32(vb.w);
        }
        __syncthreads();

#pragma unroll
        for (int q = 0; q < 8; q++) {
            const int k0 = q * 8;
            uint32_t a[2][4];
#pragma unroll
            for (int mi = 0; mi < 2; mi++) {
                const uint32_t* base = sA + (wr * 32 + mi * 16 + g) * PSTR + k0 + tig;
                a[mi][0] = base[0];
                a[mi][1] = base[8 * PSTR];
                a[mi][2] = base[4];
                a[mi][3] = base[8 * PSTR + 4];
            }
#pragma unroll
            for (int ni = 0; ni < 8; ni++) {
                const uint32_t* bb = sB + (wc * 64 + ni * 8 + g) * PSTR + k0 + tig;
                uint32_t b0 = bb[0], b1 = bb[4];
#pragma unroll
                for (int mi = 0; mi < 2; mi++) mma_tf32(d[mi][ni], a[mi], b0, b1);
            }
        }
    }

    float* C = (MODE == 0) ? g_a : g_n;
#pragma unroll
    for (int mi = 0; mi < 2; mi++) {
        int gr = row0 + wr * 32 + mi * 16 + g;
#pragma unroll
        for (int ni = 0; ni < 8; ni++) {
            int gc = col0 + wc * 64 + ni * 8 + tig * 2;
            float bs0 = bias[gc], bs1 = bias[gc + 1];
            float v0 = d[mi][ni][0] + bs0;
            float v1 = d[mi][ni][1] + bs1;
            float v2 = d[mi][ni][2] + bs0;
            float v3 = d[mi][ni][3] + bs1;
            if (MODE == 0) {
                v0 = v0 > 0.f ? v0 : expm1f(v0);
                v1 = v1 > 0.f ? v1 : expm1f(v1);
                v2 = v2 > 0.f ? v2 : expm1f(v2);
                v3 = v3 > 0.f ? v3 : expm1f(v3);
            }
            C[(size_t)gr * DDIM + gc]           = v0;
            C[(size_t)gr * DDIM + gc + 1]       = v1;
            C[(size_t)(gr + 8) * DDIM + gc]     = v2;
            C[(size_t)(gr + 8) * DDIM + gc + 1] = v3;
        }
    }
}

// ---------------------------------------------------------------------------
// Fused: L2-normalize rows i and i+NHALF, exact fp32 s12, emit e4m3(n*16).
// Also zeroes the row-sum accumulators.
// ---------------------------------------------------------------------------
__global__ void norm2_kernel() {
    int i = blockIdx.x;
    int t = threadIdx.x;
    if (t == 64)  { g_rs_same[i] = 0.f;  g_rs_cross[i] = 0.f; }
    if (t == 128) { g_rs_same[i + NHALF] = 0.f; g_rs_cross[i + NHALF] = 0.f; }
    float x1 = g_n[(size_t)i * DDIM + t];
    float x2 = g_n[(size_t)(i + NHALF) * DDIM + t];
    float s1 = x1 * x1, s2 = x2 * x2, dp = x1 * x2;
#pragma unroll
    for (int o = 16; o; o >>= 1) {
        s1 += __shfl_xor_sync(0xffffffffu, s1, o);
        s2 += __shfl_xor_sync(0xffffffffu, s2, o);
        dp += __shfl_xor_sync(0xffffffffu, dp, o);
    }
    __shared__ float ws[3][8];
    if ((t & 31) == 0) { ws[0][t >> 5] = s1; ws[1][t >> 5] = s2; ws[2][t >> 5] = dp; }
    __syncthreads();
    float t1 = 0.f, t2 = 0.f, td = 0.f;
#pragma unroll
    for (int w = 0; w < 8; w++) { t1 += ws[0][w]; t2 += ws[1][w]; td += ws[2][w]; }
    float inv1 = 16.f / fmaxf(sqrtf(t1), 1e-12f);   // scale by 16 for e4m3
    float inv2 = 16.f / fmaxf(sqrtf(t2), 1e-12f);
    float v1 = x1 * inv1;
    float v2 = x2 * inv2;
    float n1 = __shfl_down_sync(0xffffffffu, v1, 1);
    float n2 = __shfl_down_sync(0xffffffffu, v2, 1);
    if ((t & 1) == 0) {
        *(uint16_t*)(g_n8 + (size_t)i * DDIM + t)           = f2e4m3x2(v1, n1);
        *(uint16_t*)(g_n8 + (size_t)(i + NHALF) * DDIM + t) = f2e4m3x2(v2, n2);
    }
    if (t == 0) g_s12[i] = td * inv1 * inv2 * 0.00390625f;  // /256 undo 16*16
}

// ---------------------------------------------------------------------------
// Gram + exp + reductions via e4m3 mma.sync m16n8k32. 128x128x256 per CTA.
// Single wait + ONE barrier, then a fully unrolled barrier-free 8-kstep
// mainloop (ptxas pipelines LDSM across ksteps). 2 CTAs/SM.
// ---------------------------------------------------------------------------
__global__ void __launch_bounds__(256, 2)
sim_mma()
{
    extern __shared__ char smem[];

    const int t = blockIdx.x;
    int bi = (int)((257.0 - sqrt(66049.0 - 8.0 * (double)t)) * 0.5);
    if (bi < 0) bi = 0;
    if (bi > 127) bi = 127;
    while (bi > 0 && bi * (257 - bi) / 2 > t) bi--;
    while (bi < 127 && (bi + 1) * (257 - (bi + 1)) / 2 <= t) bi++;
    const int bj = bi + (t - bi * (257 - bi) / 2);

    const int tid = threadIdx.x;
    const int wid = tid >> 5, lane = tid & 31;
    const int wr = wid & 3, wc = wid >> 2;
    const int row0 = bi * 128, col0 = bj * 128;

    const uint32_t s0 = smem_u32(smem);
    const char* srcA = (const char*)g_n8 + (size_t)row0 * DDIM;
    const char* srcB = (const char*)g_n8 + (size_t)col0 * DDIM;

    const int lr = tid >> 3;            // 0..31 row base group (x4 iters)
    const int lcb = (tid & 7) * 16;     // byte within 128B chunk row

    auto issue_chunk = [&](int c, int s) {
        uint32_t dA = s0 + s * STAGE_BYTES;
        uint32_t dB = dA + CHUNK_BYTES;
        const char* sa = srcA + c * 128 + lcb;
        const char* sb = srcB + c * 128 + lcb;
#pragma unroll
        for (int it = 0; it < 4; it++) {
            int r = lr + it * 32;
            CP_ASYNC16(dA + r * CSTR + lcb, sa + (size_t)r * DDIM);
            CP_ASYNC16(dB + r * CSTR + lcb, sb + (size_t)r * DDIM);
        }
        CP_COMMIT();
    };

    issue_chunk(0, 0);
    issue_chunk(1, 1);

    float d[2][8][4];
#pragma unroll
    for (int mi = 0; mi < 2; mi++)
#pragma unroll
        for (int ni = 0; ni < 8; ni++)
#pragma unroll
            for (int q = 0; q < 4; q++) d[mi][ni][q] = 0.f;

    const int lrow = lane & 15;
    const int lkof = (lane >> 4) * 16;

    // hoisted ldsm offsets (relative to stage base)
    const uint32_t offA0 = (uint32_t)((wr * 32 + lrow) * CSTR + lkof);
    const uint32_t offA1 = offA0 + 16 * CSTR;
    const uint32_t offB0 = (uint32_t)(CHUNK_BYTES + (wc * 64 + lrow) * CSTR + lkof);
    const uint32_t offB1 = offB0 + 16 * CSTR;
    const uint32_t offB2 = offB0 + 32 * CSTR;
    const uint32_t offB3 = offB0 + 48 * CSTR;

    // both chunks were committed together; wait once, sync once, then a
    // barrier-free straight-line mainloop over all 8 ksteps.
    CP_WAIT(0);
    __syncthreads();

#pragma unroll
    for (int k = 0; k < 8; k++) {
        const uint32_t kb = s0 + (k >> 2) * STAGE_BYTES + (k & 3) * 32;
        uint32_t a[2][4];
        ldsm4(a[0][0], a[0][1], a[0][2], a[0][3], kb + offA0);
        ldsm4(a[1][0], a[1][1], a[1][2], a[1][3], kb + offA1);
        uint32_t b0[8], b1[8];
        {
            uint32_t q0, q1, q2, q3;
            ldsm4(q0, q1, q2, q3, kb + offB0);
            b0[0] = q0; b1[0] = q2; b0[1] = q1; b1[1] = q3;
            ldsm4(q0, q1, q2, q3, kb + offB1);
            b0[2] = q0; b1[2] = q2; b0[3] = q1; b1[3] = q3;
            ldsm4(q0, q1, q2, q3, kb + offB2);
            b0[4] = q0; b1[4] = q2; b0[5] = q1; b1[5] = q3;
            ldsm4(q0, q1, q2, q3, kb + offB3);
            b0[6] = q0; b1[6] = q2; b0[7] = q1; b1[7] = q3;
        }
#pragma unroll
        for (int mi = 0; mi < 2; mi++)
#pragma unroll
            for (int ni = 0; ni < 8; ni++)
                mma_fp8(d[mi][ni], a[mi], b0[ni], b1[ni]);
    }

    // ---- epilogue: exp2(acc * ESC2), row sums, col sums ----
    // (row-sum part needs no sync: per-warp registers + global atomics)
    const bool same = ((bi < 64) == (bj < 64));
    float* rs = same ? g_rs_same : g_rs_cross;
    // (2/256) * log2(e): fold operand descale, 1/tau, and ex2 base change
    const float ESC2 = 0.011271059930f;

    float cp0[8], cp1[8];
#pragma unroll
    for (int ni = 0; ni < 8; ni++) { cp0[ni] = 0.f; cp1[ni] = 0.f; }

#pragma unroll
    for (int mi = 0; mi < 2; mi++) {
        float rp0 = 0.f, rp1 = 0.f;
#pragma unroll
        for (int ni = 0; ni < 8; ni++) {
            float e0 = ex2(ESC2 * d[mi][ni][0]);
            float e1 = ex2(ESC2 * d[mi][ni][1]);
            float e2 = ex2(ESC2 * d[mi][ni][2]);
            float e3 = ex2(ESC2 * d[mi][ni][3]);
            rp0 += e0 + e1;  rp1 += e2 + e3;
            cp0[ni] += e0 + e2;  cp1[ni] += e1 + e3;
        }
        rp0 += __shfl_xor_sync(0xffffffffu, rp0, 1);
        rp0 += __shfl_xor_sync(0xffffffffu, rp0, 2);
        rp1 += __shfl_xor_sync(0xffffffffu, rp1, 1);
        rp1 += __shfl_xor_sync(0xffffffffu, rp1, 2);
        if ((lane & 3) == 0) {
            int br = row0 + wr * 32 + mi * 16 + (lane >> 2);
            atomicAdd(&rs[br], rp0);
            atomicAdd(&rs[br + 8], rp1);
        }
    }

    if (bi != bj) {
#pragma unroll
        for (int ni = 0; ni < 8; ni++) {
            cp0[ni] += __shfl_xor_sync(0xffffffffu, cp0[ni], 4);
            cp0[ni] += __shfl_xor_sync(0xffffffffu, cp0[ni], 8);
            cp0[ni] += __shfl_xor_sync(0xffffffffu, cp0[ni], 16);
            cp1[ni] += __shfl_xor_sync(0xffffffffu, cp1[ni], 4);
            cp1[ni] += __shfl_xor_sync(0xffffffffu, cp1[ni], 8);
            cp1[ni] += __shfl_xor_sync(0xffffffffu, cp1[ni], 16);
        }
        __syncthreads();             // stages fully consumed before red reuse
        float* red = (float*)smem;
        if (lane < 4) {
#pragma unroll
            for (int ni = 0; ni < 8; ni++) {
                red[wid * 72 + ni * 8 + lane * 2]     = cp0[ni];
                red[wid * 72 + ni * 8 + lane * 2 + 1] = cp1[ni];
            }
        }
        __syncthreads();
        if (tid < 128) {
            int cwc = tid >> 6;
            int idx = tid & 63;
            float s = red[(cwc * 4 + 0) * 72 + idx]
                    + red[(cwc * 4 + 1) * 72 + idx]
                    + red[(cwc * 4 + 2) * 72 + idx]
                    + red[(cwc * 4 + 3) * 72 + idx];
            atomicAdd(&rs[col0 + tid], s);
        }
    }
}

__global__ void finalize_kernel(float* __restrict__ out) {
    int i = blockIdx.x * blockDim.x + threadIdx.x;
    if (i >= NHALF) return;
    const float E2 = 7.389056098930650f;   // exp(2) diagonal term (||n||=1)
    float den1 = g_rs_same[i] + g_rs_cross[i] - E2;
    float den2 = g_rs_same[i + NHALF] + g_rs_cross[i + NHALF] - E2;
    float twos = 2.0f * g_s12[i];
    out[i] = 0.5f * ((logf(den1) - twos) + (logf(den2) - twos));
}

extern "C" void kernel_launch(void* const* d_in, const int* in_sizes, int n_in,
                              void* d_out, int out_size) {
    const float* z1 = (const float*)d_in[0];
    const float* z2 = (const float*)d_in[1];
    const float* W1 = (const float*)d_in[2];
    const float* b1 = (const float*)d_in[3];
    const float* W2 = (const float*)d_in[4];
    const float* b2 = (const float*)d_in[5];
    float* out = (float*)d_out;

    cudaFuncSetAttribute(sim_mma, cudaFuncAttributeMaxDynamicSharedMemorySize,
                         SIM_SMEM);
    cudaFuncSetAttribute(proj_tc<0>, cudaFuncAttributeMaxDynamicSharedMemorySize,
                         PROJ_SMEM);
    cudaFuncSetAttribute(proj_tc<1>, cudaFuncAttributeMaxDynamicSharedMemorySize,
                         PROJ_SMEM);

    proj_tc<0><<<dim3(2, 128), 256, PROJ_SMEM>>>(z1, z2, W1, b1);
    proj_tc<1><<<dim3(2, 128), 256, PROJ_SMEM>>>(nullptr, nullptr, W2, b2);
    norm2_kernel<<<NHALF, 256>>>();
    sim_mma<<<NTILE_LIN, 256, SIM_SMEM>>>();
    finalize_kernel<<<NHALF / 256, 256>>>(out);
}